// round 1
// baseline (speedup 1.0000x reference)
#include <cuda_runtime.h>
#include <math.h>

#define QDIM   2048
#define DIM_IN 2048
#define LATENT 1024
#define N_ROIS 4096
#define N_BANK 8192
#define LN_EPS 1e-5f

// ---------------- scratch (static device memory; no allocation) ----------------
__device__ float g_Q [(size_t)N_ROIS * 2048];            //  32 MB  (q1|q2)
__device__ float g_KV[(size_t)N_BANK * 4096];            // 128 MB  (k1|v1|k2|v2)
__device__ float g_S [(size_t)2 * N_ROIS * N_BANK];      // 256 MB  (scores, 2 branches)
__device__ float g_F [(size_t)2 * N_ROIS * LATENT];      //  32 MB  (f1|f2)
__device__ float g_X [(size_t)N_ROIS * LATENT];          //  16 MB  (post-LN)
__device__ float g_rmax[2 * N_ROIS];
__device__ float g_rsum[2 * N_ROIS];

// ---------------- tiled SGEMM: C[M,N] = alpha * A * op(B) (+bias) (*1/rowsum) --
// A: row-major [M,K] lda
// B_NT:  B row-major [N,K] ldb  (C = A * B^T)
// !B_NT: B row-major [K,N] ldb  (C = A * B)
// A_EXP: A element -> __expf(a - rmax[row])
// BIAS:  += bias[n] after alpha
// ROWSCALE: *= 1/rsum[row] at the end
template<bool B_NT, bool A_EXP, bool BIAS, bool ROWSCALE>
__global__ __launch_bounds__(256)
void sgemm_kernel(const float* __restrict__ A, int lda,
                  const float* __restrict__ B, int ldb,
                  float* __restrict__ C, int ldc, int K, float alpha,
                  const float* __restrict__ bias,
                  const float* __restrict__ rmax,
                  const float* __restrict__ rsum)
{
    const int BM = 128, BN = 128, BK = 16;
    __shared__ __align__(16) float As[BK][BM + 4];
    __shared__ __align__(16) float Bs[BK][BN + 4];

    const int row0 = blockIdx.y * BM;
    const int n0   = blockIdx.x * BN;
    const int t    = threadIdx.x;
    const int ty   = t >> 4;   // 0..15 (M dir)
    const int tx   = t & 15;   // 0..15 (N dir)

    float acc[8][8];
#pragma unroll
    for (int i = 0; i < 8; i++)
#pragma unroll
        for (int j = 0; j < 8; j++) acc[i][j] = 0.f;

    for (int k0 = 0; k0 < K; k0 += BK) {
        // ---- load A tile (always K-contiguous), transpose into As[k][m]
#pragma unroll
        for (int it = 0; it < 2; ++it) {
            int task = t + it * 256;          // 0..511
            int m  = task >> 2;               // 0..127
            int kq = (task & 3) << 2;         // 0,4,8,12
            float4 v = *reinterpret_cast<const float4*>(
                A + (size_t)(row0 + m) * lda + k0 + kq);
            if (A_EXP) {
                float mx = rmax[row0 + m];
                v.x = __expf(v.x - mx); v.y = __expf(v.y - mx);
                v.z = __expf(v.z - mx); v.w = __expf(v.w - mx);
            }
            As[kq + 0][m] = v.x; As[kq + 1][m] = v.y;
            As[kq + 2][m] = v.z; As[kq + 3][m] = v.w;
        }
        // ---- load B tile
        if (B_NT) {
#pragma unroll
            for (int it = 0; it < 2; ++it) {
                int task = t + it * 256;
                int n  = task >> 2;
                int kq = (task & 3) << 2;
                float4 v = *reinterpret_cast<const float4*>(
                    B + (size_t)(n0 + n) * ldb + k0 + kq);
                Bs[kq + 0][n] = v.x; Bs[kq + 1][n] = v.y;
                Bs[kq + 2][n] = v.z; Bs[kq + 3][n] = v.w;
            }
        } else {
#pragma unroll
            for (int it = 0; it < 2; ++it) {
                int task = t + it * 256;
                int kk = task >> 5;            // 0..15
                int nq = (task & 31) << 2;     // 0..124
                float4 v = *reinterpret_cast<const float4*>(
                    B + (size_t)(k0 + kk) * ldb + n0 + nq);
                *reinterpret_cast<float4*>(&Bs[kk][nq]) = v;
            }
        }
        __syncthreads();

#pragma unroll
        for (int k = 0; k < BK; k++) {
            float a[8], b[8];
            *reinterpret_cast<float4*>(&a[0]) = *reinterpret_cast<const float4*>(&As[k][ty * 8]);
            *reinterpret_cast<float4*>(&a[4]) = *reinterpret_cast<const float4*>(&As[k][ty * 8 + 4]);
            *reinterpret_cast<float4*>(&b[0]) = *reinterpret_cast<const float4*>(&Bs[k][tx * 8]);
            *reinterpret_cast<float4*>(&b[4]) = *reinterpret_cast<const float4*>(&Bs[k][tx * 8 + 4]);
#pragma unroll
            for (int i = 0; i < 8; i++)
#pragma unroll
                for (int j = 0; j < 8; j++)
                    acc[i][j] = fmaf(a[i], b[j], acc[i][j]);
        }
        __syncthreads();
    }

    // ---- epilogue
    const int cm = row0 + ty * 8;
    const int cn = n0 + tx * 8;
#pragma unroll
    for (int i = 0; i < 8; i++) {
        float rs = 1.f;
        if (ROWSCALE) rs = 1.f / rsum[cm + i];
#pragma unroll
        for (int j4 = 0; j4 < 8; j4 += 4) {
            float4 v;
            v.x = acc[i][j4 + 0] * alpha;
            v.y = acc[i][j4 + 1] * alpha;
            v.z = acc[i][j4 + 2] * alpha;
            v.w = acc[i][j4 + 3] * alpha;
            if (BIAS) {
                v.x += bias[cn + j4 + 0]; v.y += bias[cn + j4 + 1];
                v.z += bias[cn + j4 + 2]; v.w += bias[cn + j4 + 3];
            }
            if (ROWSCALE) { v.x *= rs; v.y *= rs; v.z *= rs; v.w *= rs; }
            *reinterpret_cast<float4*>(C + (size_t)(cm + i) * ldc + cn + j4) = v;
        }
    }
}

// ---------------- per-row softmax stats (max, sum of exp) ----------------------
__global__ __launch_bounds__(256)
void rowstat_kernel(const float* __restrict__ S,
                    float* __restrict__ rmax, float* __restrict__ rsum)
{
    const int row = blockIdx.x;       // 0..8191 (both branches)
    const float4* sr = reinterpret_cast<const float4*>(S + (size_t)row * N_BANK);
    const int t = threadIdx.x, lane = t & 31, w = t >> 5;
    __shared__ float redm[8];
    __shared__ float reds[8];
    __shared__ float Msh;

    float m = -1e30f;
    for (int i = t; i < N_BANK / 4; i += 256) {
        float4 v = sr[i];
        m = fmaxf(m, fmaxf(fmaxf(v.x, v.y), fmaxf(v.z, v.w)));
    }
#pragma unroll
    for (int off = 16; off > 0; off >>= 1)
        m = fmaxf(m, __shfl_xor_sync(0xffffffffu, m, off));
    if (lane == 0) redm[w] = m;
    __syncthreads();
    if (t == 0) {
        float mm = redm[0];
#pragma unroll
        for (int i = 1; i < 8; i++) mm = fmaxf(mm, redm[i]);
        Msh = mm;
    }
    __syncthreads();
    const float M = Msh;

    float s = 0.f;
    for (int i = t; i < N_BANK / 4; i += 256) {
        float4 v = sr[i];
        s += __expf(v.x - M) + __expf(v.y - M) + __expf(v.z - M) + __expf(v.w - M);
    }
#pragma unroll
    for (int off = 16; off > 0; off >>= 1)
        s += __shfl_xor_sync(0xffffffffu, s, off);
    if (lane == 0) reds[w] = s;
    __syncthreads();
    if (t == 0) {
        float ss = 0.f;
#pragma unroll
        for (int i = 0; i < 8; i++) ss += reds[i];
        rmax[row] = M;
        rsum[row] = ss;
    }
}

// ---------------- gate (f1*f2) + LayerNorm + PReLU -----------------------------
__global__ __launch_bounds__(256)
void gate_ln_kernel(const float* __restrict__ F,
                    const float* __restrict__ ln_w, const float* __restrict__ ln_b,
                    const float* __restrict__ prelu_a,
                    float* __restrict__ X)
{
    const int row = blockIdx.x;       // 0..4095
    const int t = threadIdx.x, lane = t & 31, w = t >> 5;
    const float4 f1 = reinterpret_cast<const float4*>(F + (size_t)row * LATENT)[t];
    const float4 f2 = reinterpret_cast<const float4*>(F + (size_t)(N_ROIS + row) * LATENT)[t];
    float4 c;
    c.x = f1.x * f2.x; c.y = f1.y * f2.y; c.z = f1.z * f2.z; c.w = f1.w * f2.w;

    __shared__ float red[8];
    __shared__ float mu_sh, var_sh;

    float s = c.x + c.y + c.z + c.w;
#pragma unroll
    for (int off = 16; off > 0; off >>= 1) s += __shfl_xor_sync(0xffffffffu, s, off);
    if (lane == 0) red[w] = s;
    __syncthreads();
    if (t == 0) {
        float ss = 0.f;
#pragma unroll
        for (int i = 0; i < 8; i++) ss += red[i];
        mu_sh = ss * (1.f / LATENT);
    }
    __syncthreads();
    const float mu = mu_sh;

    float dx = c.x - mu, dy = c.y - mu, dz = c.z - mu, dw = c.w - mu;
    float sq = dx * dx + dy * dy + dz * dz + dw * dw;
#pragma unroll
    for (int off = 16; off > 0; off >>= 1) sq += __shfl_xor_sync(0xffffffffu, sq, off);
    __syncthreads();   // red reuse
    if (lane == 0) red[w] = sq;
    __syncthreads();
    if (t == 0) {
        float ss = 0.f;
#pragma unroll
        for (int i = 0; i < 8; i++) ss += red[i];
        var_sh = ss * (1.f / LATENT);
    }
    __syncthreads();
    const float inv = rsqrtf(var_sh + LN_EPS);
    const float slope = prelu_a[0];

    const float4 wv = reinterpret_cast<const float4*>(ln_w)[t];
    const float4 bv = reinterpret_cast<const float4*>(ln_b)[t];
    float4 x;
    x.x = dx * inv * wv.x + bv.x;
    x.y = dy * inv * wv.y + bv.y;
    x.z = dz * inv * wv.z + bv.z;
    x.w = dw * inv * wv.w + bv.w;
    x.x = x.x >= 0.f ? x.x : slope * x.x;
    x.y = x.y >= 0.f ? x.y : slope * x.y;
    x.z = x.z >= 0.f ? x.z : slope * x.z;
    x.w = x.w >= 0.f ? x.w : slope * x.w;
    reinterpret_cast<float4*>(X + (size_t)row * LATENT)[t] = x;
}

// ---------------- launch --------------------------------------------------------
extern "C" void kernel_launch(void* const* d_in, const int* in_sizes, int n_in,
                              void* d_out, int out_size)
{
    const float* feat     = (const float*)d_in[0];
    const float* key_bank = (const float*)d_in[1];
    const float* Wc1 = (const float*)d_in[2];  const float* bc1 = (const float*)d_in[3];
    const float* Wc2 = (const float*)d_in[4];  const float* bc2 = (const float*)d_in[5];
    const float* Wc3 = (const float*)d_in[6];  const float* bc3 = (const float*)d_in[7];
    const float* Wd1 = (const float*)d_in[8];  const float* bd1 = (const float*)d_in[9];
    const float* Wd2 = (const float*)d_in[10]; const float* bd2 = (const float*)d_in[11];
    const float* Wd3 = (const float*)d_in[12]; const float* bd3 = (const float*)d_in[13];
    const float* ln_w = (const float*)d_in[14];
    const float* ln_b = (const float*)d_in[15];
    const float* prelu_a = (const float*)d_in[16];
    const float* Wffn = (const float*)d_in[17];
    const float* bffn = (const float*)d_in[18];
    float* out = (float*)d_out;

    void *pQ, *pKV, *pS, *pF, *pX, *pRM, *pRS;
    cudaGetSymbolAddress(&pQ,  g_Q);
    cudaGetSymbolAddress(&pKV, g_KV);
    cudaGetSymbolAddress(&pS,  g_S);
    cudaGetSymbolAddress(&pF,  g_F);
    cudaGetSymbolAddress(&pX,  g_X);
    cudaGetSymbolAddress(&pRM, g_rmax);
    cudaGetSymbolAddress(&pRS, g_rsum);
    float* Q  = (float*)pQ;
    float* KV = (float*)pKV;
    float* S  = (float*)pS;
    float* F  = (float*)pF;
    float* X  = (float*)pX;
    float* RM = (float*)pRM;
    float* RS = (float*)pRS;

    const dim3 blk(256);
    const float inv_sqrt_l = 0.03125f;   // 1/sqrt(1024)

    // ---- projections (NT, +bias)
    // q1 | q2 into Q[4096 x 2048]
    sgemm_kernel<true,false,true,false><<<dim3(8, 32), blk>>>(
        feat, QDIM, Wc1, QDIM, Q, 2048, QDIM, 1.f, bc1, nullptr, nullptr);
    sgemm_kernel<true,false,true,false><<<dim3(8, 32), blk>>>(
        feat, QDIM, Wd1, QDIM, Q + LATENT, 2048, QDIM, 1.f, bd1, nullptr, nullptr);
    // k1 | v1 | k2 | v2 into KV[8192 x 4096]
    sgemm_kernel<true,false,true,false><<<dim3(8, 64), blk>>>(
        key_bank, DIM_IN, Wc2, DIM_IN, KV + 0 * LATENT, 4096, DIM_IN, 1.f, bc2, nullptr, nullptr);
    sgemm_kernel<true,false,true,false><<<dim3(8, 64), blk>>>(
        key_bank, DIM_IN, Wc3, DIM_IN, KV + 1 * LATENT, 4096, DIM_IN, 1.f, bc3, nullptr, nullptr);
    sgemm_kernel<true,false,true,false><<<dim3(8, 64), blk>>>(
        key_bank, DIM_IN, Wd2, DIM_IN, KV + 2 * LATENT, 4096, DIM_IN, 1.f, bd2, nullptr, nullptr);
    sgemm_kernel<true,false,true,false><<<dim3(8, 64), blk>>>(
        key_bank, DIM_IN, Wd3, DIM_IN, KV + 3 * LATENT, 4096, DIM_IN, 1.f, bd3, nullptr, nullptr);

    // ---- scores S = (Q K^T) / sqrt(L)   (NT, alpha)
    sgemm_kernel<true,false,false,false><<<dim3(64, 32), blk>>>(
        Q,          2048, KV + 0 * LATENT, 4096, S,                            N_BANK, LATENT,
        inv_sqrt_l, nullptr, nullptr, nullptr);
    sgemm_kernel<true,false,false,false><<<dim3(64, 32), blk>>>(
        Q + LATENT, 2048, KV + 2 * LATENT, 4096, S + (size_t)N_ROIS * N_BANK, N_BANK, LATENT,
        inv_sqrt_l, nullptr, nullptr, nullptr);

    // ---- per-row softmax stats (both branches: 8192 rows)
    rowstat_kernel<<<2 * N_ROIS, blk>>>(S, RM, RS);

    // ---- O = softmax(S) V   (NN, A_EXP, rowscale)
    sgemm_kernel<false,true,false,true><<<dim3(8, 32), blk>>>(
        S,                            N_BANK, KV + 1 * LATENT, 4096, F,                            LATENT,
        N_BANK, 1.f, nullptr, RM,          RS);
    sgemm_kernel<false,true,false,true><<<dim3(8, 32), blk>>>(
        S + (size_t)N_ROIS * N_BANK,  N_BANK, KV + 3 * LATENT, 4096, F + (size_t)N_ROIS * LATENT, LATENT,
        N_BANK, 1.f, nullptr, RM + N_ROIS, RS + N_ROIS);

    // ---- gate + LN + PReLU
    gate_ln_kernel<<<N_ROIS, blk>>>(F, ln_w, ln_b, prelu_a, X);

    // ---- FFN: out = X Wffn^T + bffn  (NT, +bias)
    sgemm_kernel<true,false,true,false><<<dim3(16, 32), blk>>>(
        X, LATENT, Wffn, LATENT, out, DIM_IN, LATENT, 1.f, bffn, nullptr, nullptr);
}

// round 3
// speedup vs baseline: 2.2514x; 2.2514x over previous
#include <cuda_runtime.h>
#include <cuda_bf16.h>
#include <cstdint>
#include <math.h>

#define DIM_IN 2048
#define QDIM   2048
#define LATENT 1024
#define N_ROIS 4096
#define N_BANK 8192
#define LN_EPS 1e-5f

// ============================ static scratch ====================================
__device__ __nv_bfloat16 g_feat_h[(size_t)N_ROIS * QDIM];
__device__ __nv_bfloat16 g_feat_l[(size_t)N_ROIS * QDIM];
__device__ __nv_bfloat16 g_kb_h[(size_t)N_BANK * DIM_IN];
__device__ __nv_bfloat16 g_kb_l[(size_t)N_BANK * DIM_IN];
#define WSZ ((size_t)LATENT * QDIM)
__device__ __nv_bfloat16 g_W_h[7 * WSZ];
__device__ __nv_bfloat16 g_W_l[7 * WSZ];
__device__ __nv_bfloat16 g_Q_h[(size_t)2 * N_ROIS * LATENT];
__device__ __nv_bfloat16 g_Q_l[(size_t)2 * N_ROIS * LATENT];
__device__ __nv_bfloat16 g_K_h[(size_t)2 * N_BANK * LATENT];
__device__ __nv_bfloat16 g_K_l[(size_t)2 * N_BANK * LATENT];
__device__ __nv_bfloat16 g_Vt_h[(size_t)2 * LATENT * N_BANK];
__device__ __nv_bfloat16 g_Vt_l[(size_t)2 * LATENT * N_BANK];
__device__ float         g_S  [(size_t)2 * N_ROIS * N_BANK];
__device__ __nv_bfloat16 g_E_h[(size_t)2 * N_ROIS * N_BANK];
__device__ __nv_bfloat16 g_E_l[(size_t)2 * N_ROIS * N_BANK];
__device__ float         g_F  [(size_t)2 * N_ROIS * LATENT];
__device__ __nv_bfloat16 g_X_h[(size_t)N_ROIS * LATENT];
__device__ __nv_bfloat16 g_X_l[(size_t)N_ROIS * LATENT];
__device__ float g_rmax[2 * N_ROIS];
__device__ float g_rsum[2 * N_ROIS];

// ============================ PTX helpers =======================================
__device__ __forceinline__ uint32_t smem_u32(const void* p) {
    uint32_t a;
    asm("{ .reg .u64 t; cvta.to.shared.u64 t, %1; cvt.u32.u64 %0, t; }" : "=r"(a) : "l"(p));
    return a;
}
__device__ __forceinline__ void cp_async16(uint32_t s, const void* g) {
    asm volatile("cp.async.cg.shared.global [%0], [%1], 16;\n" :: "r"(s), "l"(g));
}
#define CP_COMMIT() asm volatile("cp.async.commit_group;\n" ::: "memory")
#define CP_WAIT2()  asm volatile("cp.async.wait_group 2;\n" ::: "memory")
#define CP_WAIT0()  asm volatile("cp.async.wait_group 0;\n" ::: "memory")

#define LDSM_X4(r, a)                                                               \
    asm volatile("ldmatrix.sync.aligned.m8n8.x4.shared.b16 {%0,%1,%2,%3}, [%4];"    \
        : "=r"((r)[0]), "=r"((r)[1]), "=r"((r)[2]), "=r"((r)[3]) : "r"(a))

#define MMA_BF16(c, a, b0, b1)                                                      \
    asm volatile("mma.sync.aligned.m16n8k16.row.col.f32.bf16.bf16.f32 "             \
        "{%0,%1,%2,%3}, {%4,%5,%6,%7}, {%8,%9}, {%0,%1,%2,%3};"                     \
        : "+f"((c)[0]), "+f"((c)[1]), "+f"((c)[2]), "+f"((c)[3])                    \
        : "r"((a)[0]), "r"((a)[1]), "r"((a)[2]), "r"((a)[3]), "r"(b0), "r"(b1))

// ============================ tiled split-bf16 MMA GEMM =========================
// C[M,N] = A[M,K] * B[N,K]^T; A,B given as bf16 hi/lo pairs; fp32 accumulate via
// 3 MMAs (hi*hi + hi*lo + lo*hi).
// MODE 0: split bf16 out, col-bias    (Q,K projections)
// MODE 1: split bf16 out, row-bias    (Vt = W @ key_bank^T)
// MODE 2: f32 out, *alpha             (scores)
// MODE 3: f32 out, *1/rsum[row]       (PV)
// MODE 4: f32 out, +col-bias          (FFN)
//
// Block tile 128x128x32, 8 warps (warp tile 64x32), 4-stage cp.async pipeline.
// smem tile: 128 rows x 32 halves, row stride 40 halves (80B) -> conflict-free
// ldmatrix; tile = 10240 B; stage = 4 tiles (Ah,Al,Bh,Bl) = 40960 B; 4 stages.
#define TILE_B  10240
#define STAGE_B 40960
#define SMEM_BYTES (4 * STAGE_B)

__device__ __forceinline__ void load_stage_g(uint32_t sstage,
    const __nv_bfloat16* __restrict__ Ah, const __nv_bfloat16* __restrict__ Al,
    int lda, int row0,
    const __nv_bfloat16* __restrict__ Bh, const __nv_bfloat16* __restrict__ Bl,
    int ldb, int n0, int k0, int tid)
{
#pragma unroll
    for (int it = 0; it < 2; ++it) {
        int id = tid + it * 256;          // 0..511
        int r  = id >> 2;                 // 0..127
        int cw = id & 3;                  // 16B chunk within 64B row
        uint32_t soff = (uint32_t)(r * 80 + cw * 16);
        size_t ga = (size_t)(row0 + r) * lda + k0 + cw * 8;
        size_t gb = (size_t)(n0 + r)  * ldb + k0 + cw * 8;
        cp_async16(sstage +         soff, Ah + ga);
        cp_async16(sstage + TILE_B + soff, Al + ga);
        cp_async16(sstage + 2 * TILE_B + soff, Bh + gb);
        cp_async16(sstage + 3 * TILE_B + soff, Bl + gb);
    }
}

template<int MODE>
__global__ __launch_bounds__(256, 1)
void gemm_bf16x3(const __nv_bfloat16* __restrict__ Ah, const __nv_bfloat16* __restrict__ Al, int lda,
                 const __nv_bfloat16* __restrict__ Bh, const __nv_bfloat16* __restrict__ Bl, int ldb,
                 int K,
                 float* __restrict__ Cf,
                 __nv_bfloat16* __restrict__ Ch, __nv_bfloat16* __restrict__ Cl, int ldc,
                 float alpha, const float* __restrict__ bias, const float* __restrict__ rsum)
{
    extern __shared__ __align__(16) char smem[];
    const uint32_t sbase = smem_u32(smem);
    const int tid = threadIdx.x, wid = tid >> 5, lane = tid & 31;
    const int m0 = blockIdx.y * 128, n0 = blockIdx.x * 128;
    const int wm = wid & 1;           // 0..1  (M dir, 64 rows each)
    const int wn = wid >> 1;          // 0..3  (N dir, 32 cols each)

    // lane-invariant ldmatrix byte offsets within a tile
    const uint32_t aoff = (uint32_t)((wm * 64 + (lane & 15)) * 80 + (lane >> 4) * 16);
    const uint32_t boff = (uint32_t)((wn * 32 + ((lane >> 4) & 1) * 8 + (lane & 7)) * 80
                                     + ((lane >> 3) & 1) * 16);

    float acc[4][4][4];
#pragma unroll
    for (int i = 0; i < 4; i++)
#pragma unroll
        for (int j = 0; j < 4; j++)
#pragma unroll
            for (int q = 0; q < 4; q++) acc[i][j][q] = 0.f;

    const int nc = K >> 5;

#pragma unroll 1
    for (int s = 0; s < 3; s++) {
        if (s < nc) load_stage_g(sbase + (uint32_t)s * STAGE_B, Ah, Al, lda, m0, Bh, Bl, ldb, n0, s * 32, tid);
        CP_COMMIT();
    }

#pragma unroll 1
    for (int c = 0; c < nc; c++) {
        CP_WAIT2();
        __syncthreads();
        int cn = c + 3;
        if (cn < nc)
            load_stage_g(sbase + (uint32_t)(cn & 3) * STAGE_B, Ah, Al, lda, m0, Bh, Bl, ldb, n0, cn * 32, tid);
        CP_COMMIT();

        const uint32_t st = sbase + (uint32_t)(c & 3) * STAGE_B;
        const uint32_t sAh = st, sAl = st + TILE_B, sBh = st + 2 * TILE_B, sBl = st + 3 * TILE_B;
#pragma unroll
        for (int ks = 0; ks < 2; ks++) {
            uint32_t ah[4][4], al[4][4], bh[2][4], bl[2][4];
#pragma unroll
            for (int mi = 0; mi < 4; mi++) {
                uint32_t off = aoff + (uint32_t)(mi * 1280 + ks * 32);
                LDSM_X4(ah[mi], sAh + off);
                LDSM_X4(al[mi], sAl + off);
            }
#pragma unroll
            for (int p = 0; p < 2; p++) {
                uint32_t off = boff + (uint32_t)(p * 1280 + ks * 32);
                LDSM_X4(bh[p], sBh + off);
                LDSM_X4(bl[p], sBl + off);
            }
#pragma unroll
            for (int mi = 0; mi < 4; mi++) {
#pragma unroll
                for (int p = 0; p < 2; p++) {
                    MMA_BF16(acc[mi][2 * p + 0], ah[mi], bh[p][0], bh[p][1]);
                    MMA_BF16(acc[mi][2 * p + 1], ah[mi], bh[p][2], bh[p][3]);
                    MMA_BF16(acc[mi][2 * p + 0], ah[mi], bl[p][0], bl[p][1]);
                    MMA_BF16(acc[mi][2 * p + 1], ah[mi], bl[p][2], bl[p][3]);
                    MMA_BF16(acc[mi][2 * p + 0], al[mi], bh[p][0], bh[p][1]);
                    MMA_BF16(acc[mi][2 * p + 1], al[mi], bh[p][2], bh[p][3]);
                }
            }
        }
    }

    // ---- epilogue: fragment (mi,ni): rows r0, r0+8; cols col, col+1
#pragma unroll
    for (int mi = 0; mi < 4; mi++) {
        const int r0 = m0 + wm * 64 + mi * 16 + (lane >> 2);
        const int r1 = r0 + 8;
        float s0 = 1.f, s1 = 1.f, rb0 = 0.f, rb1 = 0.f;
        if (MODE == 3) { s0 = 1.f / rsum[r0]; s1 = 1.f / rsum[r1]; }
        if (MODE == 1) { rb0 = bias[r0]; rb1 = bias[r1]; }
#pragma unroll
        for (int ni = 0; ni < 4; ni++) {
            const int col = n0 + wn * 32 + ni * 8 + 2 * (lane & 3);
            float v0 = acc[mi][ni][0], v1 = acc[mi][ni][1];
            float v2 = acc[mi][ni][2], v3 = acc[mi][ni][3];
            if (MODE == 2) { v0 *= alpha; v1 *= alpha; v2 *= alpha; v3 *= alpha; }
            if (MODE == 3) { v0 *= s0; v1 *= s0; v2 *= s1; v3 *= s1; }
            if (MODE == 4) {
                float b0 = bias[col], b1 = bias[col + 1];
                v0 += b0; v1 += b1; v2 += b0; v3 += b1;
            }
            if (MODE == 0) {
                float b0 = bias[col], b1 = bias[col + 1];
                v0 += b0; v1 += b1; v2 += b0; v3 += b1;
            }
            if (MODE == 1) { v0 += rb0; v1 += rb0; v2 += rb1; v3 += rb1; }

            if (MODE == 2 || MODE == 3 || MODE == 4) {
                *reinterpret_cast<float2*>(Cf + (size_t)r0 * ldc + col) = make_float2(v0, v1);
                *reinterpret_cast<float2*>(Cf + (size_t)r1 * ldc + col) = make_float2(v2, v3);
            } else {
                __nv_bfloat16 h0 = __float2bfloat16(v0), h1 = __float2bfloat16(v1);
                __nv_bfloat16 h2 = __float2bfloat16(v2), h3 = __float2bfloat16(v3);
                *reinterpret_cast<__nv_bfloat162*>(Ch + (size_t)r0 * ldc + col) = __halves2bfloat162(h0, h1);
                *reinterpret_cast<__nv_bfloat162*>(Ch + (size_t)r1 * ldc + col) = __halves2bfloat162(h2, h3);
                *reinterpret_cast<__nv_bfloat162*>(Cl + (size_t)r0 * ldc + col) =
                    __halves2bfloat162(__float2bfloat16(v0 - __bfloat162float(h0)),
                                       __float2bfloat16(v1 - __bfloat162float(h1)));
                *reinterpret_cast<__nv_bfloat162*>(Cl + (size_t)r1 * ldc + col) =
                    __halves2bfloat162(__float2bfloat16(v2 - __bfloat162float(h2)),
                                       __float2bfloat16(v3 - __bfloat162float(h3)));
            }
        }
    }
    CP_WAIT0();
}

// ============================ aux kernels =======================================
__global__ __launch_bounds__(256)
void split4_kernel(const float4* __restrict__ s, __nv_bfloat162* __restrict__ h,
                   __nv_bfloat162* __restrict__ l, int n4)
{
    for (int i = blockIdx.x * blockDim.x + threadIdx.x; i < n4; i += gridDim.x * blockDim.x) {
        float4 v = s[i];
        __nv_bfloat16 hx = __float2bfloat16(v.x), hy = __float2bfloat16(v.y);
        __nv_bfloat16 hz = __float2bfloat16(v.z), hw = __float2bfloat16(v.w);
        h[2 * i + 0] = __halves2bfloat162(hx, hy);
        h[2 * i + 1] = __halves2bfloat162(hz, hw);
        l[2 * i + 0] = __halves2bfloat162(__float2bfloat16(v.x - __bfloat162float(hx)),
                                          __float2bfloat16(v.y - __bfloat162float(hy)));
        l[2 * i + 1] = __halves2bfloat162(__float2bfloat16(v.z - __bfloat162float(hz)),
                                          __float2bfloat16(v.w - __bfloat162float(hw)));
    }
}

__global__ __launch_bounds__(256)
void rowstat_kernel(const float* __restrict__ S,
                    float* __restrict__ rmax, float* __restrict__ rsum)
{
    const int row = blockIdx.x;
    const float4* sr = reinterpret_cast<const float4*>(S + (size_t)row * N_BANK);
    const int t = threadIdx.x, lane = t & 31, w = t >> 5;
    __shared__ float redm[8], reds[8], Msh;

    float m = -1e30f;
    for (int i = t; i < N_BANK / 4; i += 256) {
        float4 v = sr[i];
        m = fmaxf(m, fmaxf(fmaxf(v.x, v.y), fmaxf(v.z, v.w)));
    }
#pragma unroll
    for (int off = 16; off > 0; off >>= 1) m = fmaxf(m, __shfl_xor_sync(0xffffffffu, m, off));
    if (lane == 0) redm[w] = m;
    __syncthreads();
    if (t == 0) {
        float mm = redm[0];
#pragma unroll
        for (int i = 1; i < 8; i++) mm = fmaxf(mm, redm[i]);
        Msh = mm;
    }
    __syncthreads();
    const float M = Msh;

    float s = 0.f;
    for (int i = t; i < N_BANK / 4; i += 256) {
        float4 v = sr[i];
        s += __expf(v.x - M) + __expf(v.y - M) + __expf(v.z - M) + __expf(v.w - M);
    }
#pragma unroll
    for (int off = 16; off > 0; off >>= 1) s += __shfl_xor_sync(0xffffffffu, s, off);
    if (lane == 0) reds[w] = s;
    __syncthreads();
    if (t == 0) {
        float ss = 0.f;
#pragma unroll
        for (int i = 0; i < 8; i++) ss += reds[i];
        rmax[row] = M;
        rsum[row] = ss;
    }
}

__global__ __launch_bounds__(256)
void pexp_kernel(const float4* __restrict__ S, const float* __restrict__ rmax,
                 __nv_bfloat162* __restrict__ Eh, __nv_bfloat162* __restrict__ El, int n4)
{
    for (int i = blockIdx.x * blockDim.x + threadIdx.x; i < n4; i += gridDim.x * blockDim.x) {
        const float m = rmax[i >> 11];          // 2048 float4 per row
        float4 v = S[i];
        float e0 = __expf(v.x - m), e1 = __expf(v.y - m);
        float e2 = __expf(v.z - m), e3 = __expf(v.w - m);
        __nv_bfloat16 h0 = __float2bfloat16(e0), h1 = __float2bfloat16(e1);
        __nv_bfloat16 h2 = __float2bfloat16(e2), h3 = __float2bfloat16(e3);
        Eh[2 * i + 0] = __halves2bfloat162(h0, h1);
        Eh[2 * i + 1] = __halves2bfloat162(h2, h3);
        El[2 * i + 0] = __halves2bfloat162(__float2bfloat16(e0 - __bfloat162float(h0)),
                                           __float2bfloat16(e1 - __bfloat162float(h1)));
        El[2 * i + 1] = __halves2bfloat162(__float2bfloat16(e2 - __bfloat162float(h2)),
                                           __float2bfloat16(e3 - __bfloat162float(h3)));
    }
}

__global__ __launch_bounds__(256)
void gate_ln_kernel(const float* __restrict__ F,
                    const float* __restrict__ ln_w, const float* __restrict__ ln_b,
                    const float* __restrict__ prelu_a,
                    __nv_bfloat16* __restrict__ Xh, __nv_bfloat16* __restrict__ Xl)
{
    const int row = blockIdx.x;
    const int t = threadIdx.x, lane = t & 31, w = t >> 5;
    const float4 f1 = reinterpret_cast<const float4*>(F + (size_t)row * LATENT)[t];
    const float4 f2 = reinterpret_cast<const float4*>(F + (size_t)(N_ROIS + row) * LATENT)[t];
    float4 c;
    c.x = f1.x * f2.x; c.y = f1.y * f2.y; c.z = f1.z * f2.z; c.w = f1.w * f2.w;

    __shared__ float red[8], mu_sh, var_sh;
    float s = c.x + c.y + c.z + c.w;
#pragma unroll
    for (int off = 16; off > 0; off >>= 1) s += __shfl_xor_sync(0xffffffffu, s, off);
    if (lane == 0) red[w] = s;
    __syncthreads();
    if (t == 0) {
        float ss = 0.f;
#pragma unroll
        for (int i = 0; i < 8; i++) ss += red[i];
        mu_sh = ss * (1.f / LATENT);
    }
    __syncthreads();
    const float mu = mu_sh;
    float dx = c.x - mu, dy = c.y - mu, dz = c.z - mu, dw = c.w - mu;
    float sq = dx * dx + dy * dy + dz * dz + dw * dw;
#pragma unroll
    for (int off = 16; off > 0; off >>= 1) sq += __shfl_xor_sync(0xffffffffu, sq, off);
    __syncthreads();
    if (lane == 0) red[w] = sq;
    __syncthreads();
    if (t == 0) {
        float ss = 0.f;
#pragma unroll
        for (int i = 0; i < 8; i++) ss += red[i];
        var_sh = ss * (1.f / LATENT);
    }
    __syncthreads();
    const float inv = rsqrtf(var_sh + LN_EPS);
    const float slope = prelu_a[0];
    const float4 wv = reinterpret_cast<const float4*>(ln_w)[t];
    const float4 bv = reinterpret_cast<const float4*>(ln_b)[t];
    float4 x;
    x.x = dx * inv * wv.x + bv.x;  x.y = dy * inv * wv.y + bv.y;
    x.z = dz * inv * wv.z + bv.z;  x.w = dw * inv * wv.w + bv.w;
    x.x = x.x >= 0.f ? x.x : slope * x.x;
    x.y = x.y >= 0.f ? x.y : slope * x.y;
    x.z = x.z >= 0.f ? x.z : slope * x.z;
    x.w = x.w >= 0.f ? x.w : slope * x.w;

    __nv_bfloat16 h0 = __float2bfloat16(x.x), h1 = __float2bfloat16(x.y);
    __nv_bfloat16 h2 = __float2bfloat16(x.z), h3 = __float2bfloat16(x.w);
    __nv_bfloat162* hp = reinterpret_cast<__nv_bfloat162*>(Xh + (size_t)row * LATENT);
    __nv_bfloat162* lp = reinterpret_cast<__nv_bfloat162*>(Xl + (size_t)row * LATENT);
    hp[2 * t + 0] = __halves2bfloat162(h0, h1);
    hp[2 * t + 1] = __halves2bfloat162(h2, h3);
    lp[2 * t + 0] = __halves2bfloat162(__float2bfloat16(x.x - __bfloat162float(h0)),
                                       __float2bfloat16(x.y - __bfloat162float(h1)));
    lp[2 * t + 1] = __halves2bfloat162(__float2bfloat16(x.z - __bfloat162float(h2)),
                                       __float2bfloat16(x.w - __bfloat162float(h3)));
}

// ============================ launch ============================================
static float* symf(const void* s) { void* p; cudaGetSymbolAddress(&p, s); return (float*)p; }
static __nv_bfloat16* symb(const void* s) { void* p; cudaGetSymbolAddress(&p, s); return (__nv_bfloat16*)p; }

extern "C" void kernel_launch(void* const* d_in, const int* in_sizes, int n_in,
                              void* d_out, int out_size)
{
    const float* feat     = (const float*)d_in[0];
    const float* key_bank = (const float*)d_in[1];
    const float* Wc1 = (const float*)d_in[2];  const float* bc1 = (const float*)d_in[3];
    const float* Wc2 = (const float*)d_in[4];  const float* bc2 = (const float*)d_in[5];
    const float* Wc3 = (const float*)d_in[6];  const float* bc3 = (const float*)d_in[7];
    const float* Wd1 = (const float*)d_in[8];  const float* bd1 = (const float*)d_in[9];
    const float* Wd2 = (const float*)d_in[10]; const float* bd2 = (const float*)d_in[11];
    const float* Wd3 = (const float*)d_in[12]; const float* bd3 = (const float*)d_in[13];
    const float* ln_w = (const float*)d_in[14];
    const float* ln_b = (const float*)d_in[15];
    const float* prelu_a = (const float*)d_in[16];
    const float* Wffn = (const float*)d_in[17];
    const float* bffn = (const float*)d_in[18];
    float* out = (float*)d_out;

    __nv_bfloat16 *feat_h = symb(&g_feat_h), *feat_l = symb(&g_feat_l);
    __nv_bfloat16 *kb_h = symb(&g_kb_h), *kb_l = symb(&g_kb_l);
    __nv_bfloat16 *W_h = symb(&g_W_h), *W_l = symb(&g_W_l);
    __nv_bfloat16 *Q_h = symb(&g_Q_h), *Q_l = symb(&g_Q_l);
    __nv_bfloat16 *K_h = symb(&g_K_h), *K_l = symb(&g_K_l);
    __nv_bfloat16 *Vt_h = symb(&g_Vt_h), *Vt_l = symb(&g_Vt_l);
    __nv_bfloat16 *E_h = symb(&g_E_h), *E_l = symb(&g_E_l);
    __nv_bfloat16 *X_h = symb(&g_X_h), *X_l = symb(&g_X_l);
    float *S = symf(&g_S), *F = symf(&g_F), *RM = symf(&g_rmax), *RS = symf(&g_rsum);

    cudaFuncSetAttribute(gemm_bf16x3<0>, cudaFuncAttributeMaxDynamicSharedMemorySize, SMEM_BYTES);
    cudaFuncSetAttribute(gemm_bf16x3<1>, cudaFuncAttributeMaxDynamicSharedMemorySize, SMEM_BYTES);
    cudaFuncSetAttribute(gemm_bf16x3<2>, cudaFuncAttributeMaxDynamicSharedMemorySize, SMEM_BYTES);
    cudaFuncSetAttribute(gemm_bf16x3<3>, cudaFuncAttributeMaxDynamicSharedMemorySize, SMEM_BYTES);
    cudaFuncSetAttribute(gemm_bf16x3<4>, cudaFuncAttributeMaxDynamicSharedMemorySize, SMEM_BYTES);

    const dim3 blk(256);
    const int SG = 1184;

    // ---- split-convert inputs & weights
    split4_kernel<<<SG, blk>>>((const float4*)feat, (__nv_bfloat162*)feat_h, (__nv_bfloat162*)feat_l, (int)((size_t)N_ROIS * QDIM / 4));
    split4_kernel<<<SG, blk>>>((const float4*)key_bank, (__nv_bfloat162*)kb_h, (__nv_bfloat162*)kb_l, (int)((size_t)N_BANK * DIM_IN / 4));
    const float* Ws[7] = { Wc1, Wd1, Wc2, Wd2, Wc3, Wd3, Wffn };
    for (int i = 0; i < 7; i++)
        split4_kernel<<<SG, blk>>>((const float4*)Ws[i],
            (__nv_bfloat162*)(W_h + i * WSZ), (__nv_bfloat162*)(W_l + i * WSZ), (int)(WSZ / 4));

    const size_t QO = (size_t)N_ROIS * LATENT;
    const size_t KO = (size_t)N_BANK * LATENT;
    const size_t VO = (size_t)LATENT * N_BANK;
    const size_t SO = (size_t)N_ROIS * N_BANK;

    // ---- Q projections: [4096,1024] = feat @ W^T    MODE0
    gemm_bf16x3<0><<<dim3(8, 32), blk, SMEM_BYTES>>>(feat_h, feat_l, QDIM,
        W_h + 0 * WSZ, W_l + 0 * WSZ, QDIM, QDIM, nullptr, Q_h, Q_l, LATENT, 0.f, bc1, nullptr);
    gemm_bf16x3<0><<<dim3(8, 32), blk, SMEM_BYTES>>>(feat_h, feat_l, QDIM,
        W_h + 1 * WSZ, W_l + 1 * WSZ, QDIM, QDIM, nullptr, Q_h + QO, Q_l + QO, LATENT, 0.f, bd1, nullptr);
    // ---- K projections: [8192,1024]                 MODE0
    gemm_bf16x3<0><<<dim3(8, 64), blk, SMEM_BYTES>>>(kb_h, kb_l, DIM_IN,
        W_h + 2 * WSZ, W_l + 2 * WSZ, DIM_IN, DIM_IN, nullptr, K_h, K_l, LATENT, 0.f, bc2, nullptr);
    gemm_bf16x3<0><<<dim3(8, 64), blk, SMEM_BYTES>>>(kb_h, kb_l, DIM_IN,
        W_h + 3 * WSZ, W_l + 3 * WSZ, DIM_IN, DIM_IN, nullptr, K_h + KO, K_l + KO, LATENT, 0.f, bd2, nullptr);
    // ---- Vt projections: [1024,8192] = W @ key_bank^T   MODE1 (row bias)
    gemm_bf16x3<1><<<dim3(64, 8), blk, SMEM_BYTES>>>(W_h + 4 * WSZ, W_l + 4 * WSZ, DIM_IN,
        kb_h, kb_l, DIM_IN, DIM_IN, nullptr, Vt_h, Vt_l, N_BANK, 0.f, bc3, nullptr);
    gemm_bf16x3<1><<<dim3(64, 8), blk, SMEM_BYTES>>>(W_h + 5 * WSZ, W_l + 5 * WSZ, DIM_IN,
        kb_h, kb_l, DIM_IN, DIM_IN, nullptr, Vt_h + VO, Vt_l + VO, N_BANK, 0.f, bd3, nullptr);

    // ---- scores: S = (Q K^T) / 32    MODE2
    gemm_bf16x3<2><<<dim3(64, 32), blk, SMEM_BYTES>>>(Q_h, Q_l, LATENT,
        K_h, K_l, LATENT, LATENT, S, nullptr, nullptr, N_BANK, 0.03125f, nullptr, nullptr);
    gemm_bf16x3<2><<<dim3(64, 32), blk, SMEM_BYTES>>>(Q_h + QO, Q_l + QO, LATENT,
        K_h + KO, K_l + KO, LATENT, LATENT, S + SO, nullptr, nullptr, N_BANK, 0.03125f, nullptr, nullptr);

    // ---- softmax stats + exp split
    rowstat_kernel<<<2 * N_ROIS, blk>>>(S, RM, RS);
    pexp_kernel<<<4096, blk>>>((const float4*)S, RM, (__nv_bfloat162*)E_h, (__nv_bfloat162*)E_l,
                               (int)(2 * SO / 4));

    // ---- PV: F = (E Vt^T) * 1/rsum    MODE3
    gemm_bf16x3<3><<<dim3(8, 32), blk, SMEM_BYTES>>>(E_h, E_l, N_BANK,
        Vt_h, Vt_l, N_BANK, N_BANK, F, nullptr, nullptr, LATENT, 0.f, nullptr, RS);
    gemm_bf16x3<3><<<dim3(8, 32), blk, SMEM_BYTES>>>(E_h + SO, E_l + SO, N_BANK,
        Vt_h + VO, Vt_l + VO, N_BANK, N_BANK, F + QO, nullptr, nullptr, LATENT, 0.f, nullptr, RS + N_ROIS);

    // ---- gate + LN + PReLU -> X split
    gate_ln_kernel<<<N_ROIS, blk>>>(F, ln_w, ln_b, prelu_a, X_h, X_l);

    // ---- FFN: out = X Wffn^T + bffn   MODE4
    gemm_bf16x3<4><<<dim3(16, 32), blk, SMEM_BYTES>>>(X_h, X_l, LATENT,
        W_h + 6 * WSZ, W_l + 6 * WSZ, LATENT, LATENT, out, nullptr, nullptr, DIM_IN, 0.f, bffn, nullptr);
}

// round 4
// speedup vs baseline: 2.4794x; 1.1013x over previous
#include <cuda_runtime.h>
#include <cuda_bf16.h>
#include <cstdint>
#include <math.h>

#define DIM_IN 2048
#define QDIM   2048
#define LATENT 1024
#define N_ROIS 4096
#define N_BANK 8192
#define LN_EPS 1e-5f

// ============================ static scratch ====================================
__device__ __nv_bfloat16 g_feat_h[(size_t)N_ROIS * QDIM];
__device__ __nv_bfloat16 g_feat_l[(size_t)N_ROIS * QDIM];
__device__ __nv_bfloat16 g_kb_h[(size_t)N_BANK * DIM_IN];
__device__ __nv_bfloat16 g_kb_l[(size_t)N_BANK * DIM_IN];
#define WSZ ((size_t)LATENT * QDIM)
__device__ __nv_bfloat16 g_W_h[7 * WSZ];
__device__ __nv_bfloat16 g_W_l[7 * WSZ];
__device__ __nv_bfloat16 g_Q_h[(size_t)2 * N_ROIS * LATENT];
__device__ __nv_bfloat16 g_Q_l[(size_t)2 * N_ROIS * LATENT];
__device__ __nv_bfloat16 g_K_h[(size_t)2 * N_BANK * LATENT];
__device__ __nv_bfloat16 g_K_l[(size_t)2 * N_BANK * LATENT];
__device__ __nv_bfloat16 g_Vt_h[(size_t)2 * LATENT * N_BANK];
__device__ __nv_bfloat16 g_Vt_l[(size_t)2 * LATENT * N_BANK];
__device__ float         g_S  [(size_t)2 * N_ROIS * N_BANK];
__device__ __nv_bfloat16 g_E_h[(size_t)2 * N_ROIS * N_BANK];
__device__ __nv_bfloat16 g_E_l[(size_t)2 * N_ROIS * N_BANK];
__device__ float         g_F  [(size_t)2 * N_ROIS * LATENT];
__device__ __nv_bfloat16 g_X_h[(size_t)N_ROIS * LATENT];
__device__ __nv_bfloat16 g_X_l[(size_t)N_ROIS * LATENT];
__device__ float g_rsum[2 * N_ROIS];

// ============================ PTX helpers =======================================
__device__ __forceinline__ uint32_t smem_u32(const void* p) {
    uint32_t a;
    asm("{ .reg .u64 t; cvta.to.shared.u64 t, %1; cvt.u32.u64 %0, t; }" : "=r"(a) : "l"(p));
    return a;
}
__device__ __forceinline__ void cp_async16(uint32_t s, const void* g) {
    asm volatile("cp.async.cg.shared.global [%0], [%1], 16;\n" :: "r"(s), "l"(g));
}
#define CP_COMMIT() asm volatile("cp.async.commit_group;\n" ::: "memory")
#define CP_WAIT1()  asm volatile("cp.async.wait_group 1;\n" ::: "memory")

#define LDSM_X4(r, a)                                                               \
    asm volatile("ldmatrix.sync.aligned.m8n8.x4.shared.b16 {%0,%1,%2,%3}, [%4];"    \
        : "=r"((r)[0]), "=r"((r)[1]), "=r"((r)[2]), "=r"((r)[3]) : "r"(a))

#define MMA_BF16(c, a, b0, b1)                                                      \
    asm volatile("mma.sync.aligned.m16n8k16.row.col.f32.bf16.bf16.f32 "             \
        "{%0,%1,%2,%3}, {%4,%5,%6,%7}, {%8,%9}, {%0,%1,%2,%3};"                     \
        : "+f"((c)[0]), "+f"((c)[1]), "+f"((c)[2]), "+f"((c)[3])                    \
        : "r"((a)[0]), "r"((a)[1]), "r"((a)[2]), "r"((a)[3]), "r"(b0), "r"(b1))

// ============================ tiled split-bf16 MMA GEMM =========================
// C[M,N] = A[M,K] * B[N,K]^T; A,B as bf16 hi/lo pairs; fp32 accum via
// 3 MMAs (hi*hi + hi*lo + lo*hi).
// MODE 0: split bf16 out, col-bias | 1: split out, row-bias | 2: f32 *alpha
// MODE 3: f32 *1/rsum[row]        | 4: f32 +col-bias
//
// Block tile 128x256x32, 16 warps (warp tile 64x32), 3-stage cp.async pipeline.
// A tile: 128 rows x 80B stride = 10240 B; B tile: 256 rows x 80B = 20480 B.
// stage = Ah+Al+Bh+Bl = 61440 B; 3 stages = 184320 B.
#define A_TILE_B 10240
#define B_TILE_B 20480
#define STAGE_B  61440
#define SMEM_BYTES (3 * STAGE_B)

__device__ __forceinline__ void load_stage_g(uint32_t st,
    const __nv_bfloat16* __restrict__ Ah, const __nv_bfloat16* __restrict__ Al,
    int lda, int m0,
    const __nv_bfloat16* __restrict__ Bh, const __nv_bfloat16* __restrict__ Bl,
    int ldb, int n0, int k0, int tid)
{
    {   // A: 128 rows, 4x16B chunks per row, hi+lo
        int r  = tid >> 2;
        int cw = tid & 3;
        uint32_t soff = (uint32_t)(r * 80 + cw * 16);
        size_t ga = (size_t)(m0 + r) * lda + k0 + cw * 8;
        cp_async16(st +            soff, Ah + ga);
        cp_async16(st + A_TILE_B + soff, Al + ga);
    }
#pragma unroll
    for (int it = 0; it < 2; ++it) {   // B: 256 rows
        int r  = (tid >> 2) + it * 128;
        int cw = tid & 3;
        uint32_t soff = (uint32_t)(r * 80 + cw * 16);
        size_t gb = (size_t)(n0 + r) * ldb + k0 + cw * 8;
        cp_async16(st + 2 * A_TILE_B +            soff, Bh + gb);
        cp_async16(st + 2 * A_TILE_B + B_TILE_B + soff, Bl + gb);
    }
}

template<int MODE>
__global__ __launch_bounds__(512, 1)
void gemm_bf16x3(const __nv_bfloat16* __restrict__ Ah, const __nv_bfloat16* __restrict__ Al, int lda,
                 const __nv_bfloat16* __restrict__ Bh, const __nv_bfloat16* __restrict__ Bl, int ldb,
                 int K,
                 float* __restrict__ Cf,
                 __nv_bfloat16* __restrict__ Ch, __nv_bfloat16* __restrict__ Cl, int ldc,
                 float alpha, const float* __restrict__ bias, const float* __restrict__ rsum)
{
    extern __shared__ __align__(16) char smem[];
    const uint32_t sbase = smem_u32(smem);
    const int tid = threadIdx.x, wid = tid >> 5, lane = tid & 31;
    const int m0 = blockIdx.y * 128, n0 = blockIdx.x * 256;
    const int wm = wid & 1;           // 0..1  (M dir, 64 rows)
    const int wn = wid >> 1;          // 0..7  (N dir, 32 cols)

    const uint32_t aoff = (uint32_t)((wm * 64 + (lane & 15)) * 80 + (lane >> 4) * 16);
    const uint32_t boff = (uint32_t)((wn * 32 + ((lane >> 4) & 1) * 8 + (lane & 7)) * 80
                                     + ((lane >> 3) & 1) * 16);

    float acc[4][4][4];
#pragma unroll
    for (int i = 0; i < 4; i++)
#pragma unroll
        for (int j = 0; j < 4; j++)
#pragma unroll
            for (int q = 0; q < 4; q++) acc[i][j][q] = 0.f;

    const int nc = K >> 5;

    load_stage_g(sbase, Ah, Al, lda, m0, Bh, Bl, ldb, n0, 0, tid);
    CP_COMMIT();
    if (nc > 1) load_stage_g(sbase + STAGE_B, Ah, Al, lda, m0, Bh, Bl, ldb, n0, 32, tid);
    CP_COMMIT();

#pragma unroll 1
    for (int c = 0; c < nc; c++) {
        CP_WAIT1();
        __syncthreads();
        int cn = c + 2;
        if (cn < nc)
            load_stage_g(sbase + (uint32_t)(cn % 3) * STAGE_B, Ah, Al, lda, m0, Bh, Bl, ldb, n0, cn * 32, tid);
        CP_COMMIT();

        const uint32_t st  = sbase + (uint32_t)(c % 3) * STAGE_B;
        const uint32_t sAh = st, sAl = st + A_TILE_B;
        const uint32_t sBh = st + 2 * A_TILE_B, sBl = st + 2 * A_TILE_B + B_TILE_B;
#pragma unroll
        for (int ks = 0; ks < 2; ks++) {
            uint32_t ah[4][4], al[4][4];
#pragma unroll
            for (int mi = 0; mi < 4; mi++) {
                uint32_t off = aoff + (uint32_t)(mi * 1280 + ks * 32);
                LDSM_X4(ah[mi], sAh + off);
                LDSM_X4(al[mi], sAl + off);
            }
#pragma unroll
            for (int p = 0; p < 2; p++) {
                uint32_t bh[4], bl[4];
                uint32_t off = boff + (uint32_t)(p * 1280 + ks * 32);
                LDSM_X4(bh, sBh + off);
                LDSM_X4(bl, sBl + off);
#pragma unroll
                for (int mi = 0; mi < 4; mi++) {
                    MMA_BF16(acc[mi][2 * p + 0], ah[mi], bh[0], bh[1]);
                    MMA_BF16(acc[mi][2 * p + 1], ah[mi], bh[2], bh[3]);
                    MMA_BF16(acc[mi][2 * p + 0], ah[mi], bl[0], bl[1]);
                    MMA_BF16(acc[mi][2 * p + 1], ah[mi], bl[2], bl[3]);
                    MMA_BF16(acc[mi][2 * p + 0], al[mi], bh[0], bh[1]);
                    MMA_BF16(acc[mi][2 * p + 1], al[mi], bh[2], bh[3]);
                }
            }
        }
    }

    // ---- epilogue
#pragma unroll
    for (int mi = 0; mi < 4; mi++) {
        const int r0 = m0 + wm * 64 + mi * 16 + (lane >> 2);
        const int r1 = r0 + 8;
        float s0 = 1.f, s1 = 1.f, rb0 = 0.f, rb1 = 0.f;
        if (MODE == 3) { s0 = 1.f / rsum[r0]; s1 = 1.f / rsum[r1]; }
        if (MODE == 1) { rb0 = bias[r0]; rb1 = bias[r1]; }
#pragma unroll
        for (int ni = 0; ni < 4; ni++) {
            const int col = n0 + wn * 32 + ni * 8 + 2 * (lane & 3);
            float v0 = acc[mi][ni][0], v1 = acc[mi][ni][1];
            float v2 = acc[mi][ni][2], v3 = acc[mi][ni][3];
            if (MODE == 2) { v0 *= alpha; v1 *= alpha; v2 *= alpha; v3 *= alpha; }
            if (MODE == 3) { v0 *= s0; v1 *= s0; v2 *= s1; v3 *= s1; }
            if (MODE == 0 || MODE == 4) {
                float b0 = bias[col], b1 = bias[col + 1];
                v0 += b0; v1 += b1; v2 += b0; v3 += b1;
            }
            if (MODE == 1) { v0 += rb0; v1 += rb0; v2 += rb1; v3 += rb1; }

            if (MODE == 2 || MODE == 3 || MODE == 4) {
                *reinterpret_cast<float2*>(Cf + (size_t)r0 * ldc + col) = make_float2(v0, v1);
                *reinterpret_cast<float2*>(Cf + (size_t)r1 * ldc + col) = make_float2(v2, v3);
            } else {
                __nv_bfloat16 h0 = __float2bfloat16(v0), h1 = __float2bfloat16(v1);
                __nv_bfloat16 h2 = __float2bfloat16(v2), h3 = __float2bfloat16(v3);
                *reinterpret_cast<__nv_bfloat162*>(Ch + (size_t)r0 * ldc + col) = __halves2bfloat162(h0, h1);
                *reinterpret_cast<__nv_bfloat162*>(Ch + (size_t)r1 * ldc + col) = __halves2bfloat162(h2, h3);
                *reinterpret_cast<__nv_bfloat162*>(Cl + (size_t)r0 * ldc + col) =
                    __halves2bfloat162(__float2bfloat16(v0 - __bfloat162float(h0)),
                                       __float2bfloat16(v1 - __bfloat162float(h1)));
                *reinterpret_cast<__nv_bfloat162*>(Cl + (size_t)r1 * ldc + col) =
                    __halves2bfloat162(__float2bfloat16(v2 - __bfloat162float(h2)),
                                       __float2bfloat16(v3 - __bfloat162float(h3)));
            }
        }
    }
}

// ============================ aux kernels =======================================
__global__ __launch_bounds__(256)
void split4_kernel(const float4* __restrict__ s, __nv_bfloat162* __restrict__ h,
                   __nv_bfloat162* __restrict__ l, int n4)
{
    for (int i = blockIdx.x * blockDim.x + threadIdx.x; i < n4; i += gridDim.x * blockDim.x) {
        float4 v = s[i];
        __nv_bfloat16 hx = __float2bfloat16(v.x), hy = __float2bfloat16(v.y);
        __nv_bfloat16 hz = __float2bfloat16(v.z), hw = __float2bfloat16(v.w);
        h[2 * i + 0] = __halves2bfloat162(hx, hy);
        h[2 * i + 1] = __halves2bfloat162(hz, hw);
        l[2 * i + 0] = __halves2bfloat162(__float2bfloat16(v.x - __bfloat162float(hx)),
                                          __float2bfloat16(v.y - __bfloat162float(hy)));
        l[2 * i + 1] = __halves2bfloat162(__float2bfloat16(v.z - __bfloat162float(hz)),
                                          __float2bfloat16(v.w - __bfloat162float(hw)));
    }
}

// fused: per-row max + exp-split + sum; S row cached in smem (one read of S).
__global__ __launch_bounds__(256)
void softmax_row_kernel(const float* __restrict__ S,
                        __nv_bfloat162* __restrict__ Eh, __nv_bfloat162* __restrict__ El,
                        float* __restrict__ rsum)
{
    __shared__ __align__(16) float srow[N_BANK];
    __shared__ float redm[8], reds[8], Msh;
    const int row = blockIdx.x;
    const float4* sg = reinterpret_cast<const float4*>(S + (size_t)row * N_BANK);
    float4* ss = reinterpret_cast<float4*>(srow);
    const int t = threadIdx.x, lane = t & 31, w = t >> 5;

    float m = -1e30f;
#pragma unroll
    for (int it = 0; it < 8; it++) {
        int i = t + it * 256;
        float4 v = sg[i];
        ss[i] = v;
        m = fmaxf(m, fmaxf(fmaxf(v.x, v.y), fmaxf(v.z, v.w)));
    }
#pragma unroll
    for (int off = 16; off > 0; off >>= 1) m = fmaxf(m, __shfl_xor_sync(0xffffffffu, m, off));
    if (lane == 0) redm[w] = m;
    __syncthreads();
    if (t == 0) {
        float mm = redm[0];
#pragma unroll
        for (int i = 1; i < 8; i++) mm = fmaxf(mm, redm[i]);
        Msh = mm;
    }
    __syncthreads();
    const float M = Msh;

    __nv_bfloat162* ehr = Eh + (size_t)row * (N_BANK / 2);
    __nv_bfloat162* elr = El + (size_t)row * (N_BANK / 2);
    float s = 0.f;
#pragma unroll
    for (int it = 0; it < 8; it++) {
        int i = t + it * 256;
        float4 v = ss[i];
        float e0 = __expf(v.x - M), e1 = __expf(v.y - M);
        float e2 = __expf(v.z - M), e3 = __expf(v.w - M);
        s += e0 + e1 + e2 + e3;
        __nv_bfloat16 h0 = __float2bfloat16(e0), h1 = __float2bfloat16(e1);
        __nv_bfloat16 h2 = __float2bfloat16(e2), h3 = __float2bfloat16(e3);
        ehr[2 * i + 0] = __halves2bfloat162(h0, h1);
        ehr[2 * i + 1] = __halves2bfloat162(h2, h3);
        elr[2 * i + 0] = __halves2bfloat162(__float2bfloat16(e0 - __bfloat162float(h0)),
                                            __float2bfloat16(e1 - __bfloat162float(h1)));
        elr[2 * i + 1] = __halves2bfloat162(__float2bfloat16(e2 - __bfloat162float(h2)),
                                            __float2bfloat16(e3 - __bfloat162float(h3)));
    }
#pragma unroll
    for (int off = 16; off > 0; off >>= 1) s += __shfl_xor_sync(0xffffffffu, s, off);
    if (lane == 0) reds[w] = s;
    __syncthreads();
    if (t == 0) {
        float ss2 = 0.f;
#pragma unroll
        for (int i = 0; i < 8; i++) ss2 += reds[i];
        rsum[row] = ss2;
    }
}

__global__ __launch_bounds__(256)
void gate_ln_kernel(const float* __restrict__ F,
                    const float* __restrict__ ln_w, const float* __restrict__ ln_b,
                    const float* __restrict__ prelu_a,
                    __nv_bfloat16* __restrict__ Xh, __nv_bfloat16* __restrict__ Xl)
{
    const int row = blockIdx.x;
    const int t = threadIdx.x, lane = t & 31, w = t >> 5;
    const float4 f1 = reinterpret_cast<const float4*>(F + (size_t)row * LATENT)[t];
    const float4 f2 = reinterpret_cast<const float4*>(F + (size_t)(N_ROIS + row) * LATENT)[t];
    float4 c;
    c.x = f1.x * f2.x; c.y = f1.y * f2.y; c.z = f1.z * f2.z; c.w = f1.w * f2.w;

    __shared__ float red[8], mu_sh, var_sh;
    float s = c.x + c.y + c.z + c.w;
#pragma unroll
    for (int off = 16; off > 0; off >>= 1) s += __shfl_xor_sync(0xffffffffu, s, off);
    if (lane == 0) red[w] = s;
    __syncthreads();
    if (t == 0) {
        float ss = 0.f;
#pragma unroll
        for (int i = 0; i < 8; i++) ss += red[i];
        mu_sh = ss * (1.f / LATENT);
    }
    __syncthreads();
    const float mu = mu_sh;
    float dx = c.x - mu, dy = c.y - mu, dz = c.z - mu, dw = c.w - mu;
    float sq = dx * dx + dy * dy + dz * dz + dw * dw;
#pragma unroll
    for (int off = 16; off > 0; off >>= 1) sq += __shfl_xor_sync(0xffffffffu, sq, off);
    __syncthreads();
    if (lane == 0) red[w] = sq;
    __syncthreads();
    if (t == 0) {
        float ss = 0.f;
#pragma unroll
        for (int i = 0; i < 8; i++) ss += red[i];
        var_sh = ss * (1.f / LATENT);
    }
    __syncthreads();
    const float inv = rsqrtf(var_sh + LN_EPS);
    const float slope = prelu_a[0];
    const float4 wv = reinterpret_cast<const float4*>(ln_w)[t];
    const float4 bv = reinterpret_cast<const float4*>(ln_b)[t];
    float4 x;
    x.x = dx * inv * wv.x + bv.x;  x.y = dy * inv * wv.y + bv.y;
    x.z = dz * inv * wv.z + bv.z;  x.w = dw * inv * wv.w + bv.w;
    x.x = x.x >= 0.f ? x.x : slope * x.x;
    x.y = x.y >= 0.f ? x.y : slope * x.y;
    x.z = x.z >= 0.f ? x.z : slope * x.z;
    x.w = x.w >= 0.f ? x.w : slope * x.w;

    __nv_bfloat16 h0 = __float2bfloat16(x.x), h1 = __float2bfloat16(x.y);
    __nv_bfloat16 h2 = __float2bfloat16(x.z), h3 = __float2bfloat16(x.w);
    __nv_bfloat162* hp = reinterpret_cast<__nv_bfloat162*>(Xh + (size_t)row * LATENT);
    __nv_bfloat162* lp = reinterpret_cast<__nv_bfloat162*>(Xl + (size_t)row * LATENT);
    hp[2 * t + 0] = __halves2bfloat162(h0, h1);
    hp[2 * t + 1] = __halves2bfloat162(h2, h3);
    lp[2 * t + 0] = __halves2bfloat162(__float2bfloat16(x.x - __bfloat162float(h0)),
                                       __float2bfloat16(x.y - __bfloat162float(h1)));
    lp[2 * t + 1] = __halves2bfloat162(__float2bfloat16(x.z - __bfloat162float(h2)),
                                       __float2bfloat16(x.w - __bfloat162float(h3)));
}

// ============================ launch ============================================
static float* symf(const void* s) { void* p; cudaGetSymbolAddress(&p, s); return (float*)p; }
static __nv_bfloat16* symb(const void* s) { void* p; cudaGetSymbolAddress(&p, s); return (__nv_bfloat16*)p; }

extern "C" void kernel_launch(void* const* d_in, const int* in_sizes, int n_in,
                              void* d_out, int out_size)
{
    const float* feat     = (const float*)d_in[0];
    const float* key_bank = (const float*)d_in[1];
    const float* Wc1 = (const float*)d_in[2];  const float* bc1 = (const float*)d_in[3];
    const float* Wc2 = (const float*)d_in[4];  const float* bc2 = (const float*)d_in[5];
    const float* Wc3 = (const float*)d_in[6];  const float* bc3 = (const float*)d_in[7];
    const float* Wd1 = (const float*)d_in[8];  const float* bd1 = (const float*)d_in[9];
    const float* Wd2 = (const float*)d_in[10]; const float* bd2 = (const float*)d_in[11];
    const float* Wd3 = (const float*)d_in[12]; const float* bd3 = (const float*)d_in[13];
    const float* ln_w = (const float*)d_in[14];
    const float* ln_b = (const float*)d_in[15];
    const float* prelu_a = (const float*)d_in[16];
    const float* Wffn = (const float*)d_in[17];
    const float* bffn = (const float*)d_in[18];
    float* out = (float*)d_out;

    __nv_bfloat16 *feat_h = symb(&g_feat_h), *feat_l = symb(&g_feat_l);
    __nv_bfloat16 *kb_h = symb(&g_kb_h), *kb_l = symb(&g_kb_l);
    __nv_bfloat16 *W_h = symb(&g_W_h), *W_l = symb(&g_W_l);
    __nv_bfloat16 *Q_h = symb(&g_Q_h), *Q_l = symb(&g_Q_l);
    __nv_bfloat16 *K_h = symb(&g_K_h), *K_l = symb(&g_K_l);
    __nv_bfloat16 *Vt_h = symb(&g_Vt_h), *Vt_l = symb(&g_Vt_l);
    __nv_bfloat16 *E_h = symb(&g_E_h), *E_l = symb(&g_E_l);
    __nv_bfloat16 *X_h = symb(&g_X_h), *X_l = symb(&g_X_l);
    float *S = symf(&g_S), *F = symf(&g_F), *RS = symf(&g_rsum);

    cudaFuncSetAttribute(gemm_bf16x3<0>, cudaFuncAttributeMaxDynamicSharedMemorySize, SMEM_BYTES);
    cudaFuncSetAttribute(gemm_bf16x3<1>, cudaFuncAttributeMaxDynamicSharedMemorySize, SMEM_BYTES);
    cudaFuncSetAttribute(gemm_bf16x3<2>, cudaFuncAttributeMaxDynamicSharedMemorySize, SMEM_BYTES);
    cudaFuncSetAttribute(gemm_bf16x3<3>, cudaFuncAttributeMaxDynamicSharedMemorySize, SMEM_BYTES);
    cudaFuncSetAttribute(gemm_bf16x3<4>, cudaFuncAttributeMaxDynamicSharedMemorySize, SMEM_BYTES);

    const dim3 blk(512);
    const dim3 blk256(256);
    const int SG = 1184;

    // ---- split-convert inputs & weights
    split4_kernel<<<SG, blk256>>>((const float4*)feat, (__nv_bfloat162*)feat_h, (__nv_bfloat162*)feat_l, (int)((size_t)N_ROIS * QDIM / 4));
    split4_kernel<<<SG, blk256>>>((const float4*)key_bank, (__nv_bfloat162*)kb_h, (__nv_bfloat162*)kb_l, (int)((size_t)N_BANK * DIM_IN / 4));
    const float* Ws[7] = { Wc1, Wd1, Wc2, Wd2, Wc3, Wd3, Wffn };
    for (int i = 0; i < 7; i++)
        split4_kernel<<<SG, blk256>>>((const float4*)Ws[i],
            (__nv_bfloat162*)(W_h + i * WSZ), (__nv_bfloat162*)(W_l + i * WSZ), (int)(WSZ / 4));

    const size_t QO = (size_t)N_ROIS * LATENT;
    const size_t KO = (size_t)N_BANK * LATENT;
    const size_t VO = (size_t)LATENT * N_BANK;
    const size_t SO = (size_t)N_ROIS * N_BANK;

    // ---- Q projections: [4096,1024] = feat @ W^T    MODE0
    gemm_bf16x3<0><<<dim3(4, 32), blk, SMEM_BYTES>>>(feat_h, feat_l, QDIM,
        W_h + 0 * WSZ, W_l + 0 * WSZ, QDIM, QDIM, nullptr, Q_h, Q_l, LATENT, 0.f, bc1, nullptr);
    gemm_bf16x3<0><<<dim3(4, 32), blk, SMEM_BYTES>>>(feat_h, feat_l, QDIM,
        W_h + 1 * WSZ, W_l + 1 * WSZ, QDIM, QDIM, nullptr, Q_h + QO, Q_l + QO, LATENT, 0.f, bd1, nullptr);
    // ---- K projections: [8192,1024]                 MODE0
    gemm_bf16x3<0><<<dim3(4, 64), blk, SMEM_BYTES>>>(kb_h, kb_l, DIM_IN,
        W_h + 2 * WSZ, W_l + 2 * WSZ, DIM_IN, DIM_IN, nullptr, K_h, K_l, LATENT, 0.f, bc2, nullptr);
    gemm_bf16x3<0><<<dim3(4, 64), blk, SMEM_BYTES>>>(kb_h, kb_l, DIM_IN,
        W_h + 3 * WSZ, W_l + 3 * WSZ, DIM_IN, DIM_IN, nullptr, K_h + KO, K_l + KO, LATENT, 0.f, bd2, nullptr);
    // ---- Vt projections: [1024,8192] = W @ key_bank^T   MODE1 (row bias)
    gemm_bf16x3<1><<<dim3(32, 8), blk, SMEM_BYTES>>>(W_h + 4 * WSZ, W_l + 4 * WSZ, DIM_IN,
        kb_h, kb_l, DIM_IN, DIM_IN, nullptr, Vt_h, Vt_l, N_BANK, 0.f, bc3, nullptr);
    gemm_bf16x3<1><<<dim3(32, 8), blk, SMEM_BYTES>>>(W_h + 5 * WSZ, W_l + 5 * WSZ, DIM_IN,
        kb_h, kb_l, DIM_IN, DIM_IN, nullptr, Vt_h + VO, Vt_l + VO, N_BANK, 0.f, bd3, nullptr);

    // ---- scores: S = (Q K^T) / 32    MODE2
    gemm_bf16x3<2><<<dim3(32, 32), blk, SMEM_BYTES>>>(Q_h, Q_l, LATENT,
        K_h, K_l, LATENT, LATENT, S, nullptr, nullptr, N_BANK, 0.03125f, nullptr, nullptr);
    gemm_bf16x3<2><<<dim3(32, 32), blk, SMEM_BYTES>>>(Q_h + QO, Q_l + QO, LATENT,
        K_h + KO, K_l + KO, LATENT, LATENT, S + SO, nullptr, nullptr, N_BANK, 0.03125f, nullptr, nullptr);

    // ---- fused softmax (max + exp-split + sum), one read of S
    softmax_row_kernel<<<2 * N_ROIS, blk256>>>(S, (__nv_bfloat162*)E_h, (__nv_bfloat162*)E_l, RS);

    // ---- PV: F = (E Vt^T) * 1/rsum    MODE3
    gemm_bf16x3<3><<<dim3(4, 32), blk, SMEM_BYTES>>>(E_h, E_l, N_BANK,
        Vt_h, Vt_l, N_BANK, N_BANK, F, nullptr, nullptr, LATENT, 0.f, nullptr, RS);
    gemm_bf16x3<3><<<dim3(4, 32), blk, SMEM_BYTES>>>(E_h + SO, E_l + SO, N_BANK,
        Vt_h + VO, Vt_l + VO, N_BANK, N_BANK, F + QO, nullptr, nullptr, LATENT, 0.f, nullptr, RS + N_ROIS);

    // ---- gate + LN + PReLU -> X split
    gate_ln_kernel<<<N_ROIS, blk256>>>(F, ln_w, ln_b, prelu_a, X_h, X_l);

    // ---- FFN: out = X Wffn^T + bffn   MODE4
    gemm_bf16x3<4><<<dim3(8, 32), blk, SMEM_BYTES>>>(X_h, X_l, LATENT,
        W_h + 6 * WSZ, W_l + 6 * WSZ, LATENT, LATENT, out, nullptr, nullptr, DIM_IN, 0.f, bffn, nullptr);
}